// round 1
// baseline (speedup 1.0000x reference)
#include <cuda_runtime.h>
#include <math.h>

#define NN 50000
#define NE 600000
#define D  128
#define NG 512
#define BN_EPS 1e-5f

// ---------------- scratch (device globals; no allocations) ----------------
__device__ float g_agg[NN * D];
__device__ float g_h[NN * D];        // pre-BN linear output
__device__ float g_h1[NN * D];       // conv1 output
__device__ float g_h2[NN * D];       // conv2 output
__device__ float g_stats[2 * D];     // sum, sumsq
__device__ float g_aff[2 * D];       // scale, shift
__device__ float g_pool[NG * 4 * D]; // [a1 | a2 | m1 | m2]
__device__ float g_hidden[NG * 4 * D];
__device__ int   g_src[NE];
__device__ int   g_dst[NE];
__device__ int   g_batch[NN];
__device__ int   g_flag[1];

// ---------------- dtype detect + convert ----------------
// If edge_index is int64, words[2*i+1] for i in [0,NE) are the hi-words of all
// src values (all zero, since 0 <= idx < 50000). If int32, they are real data.
__global__ void detect_k(const int* __restrict__ w) {
    int tid = blockIdx.x * blockDim.x + threadIdx.x;
    int stride = gridDim.x * blockDim.x;
    int v = 0;
    for (int i = tid; i < NE; i += stride) v |= w[2 * i + 1];
    #pragma unroll
    for (int o = 16; o > 0; o >>= 1) v |= __shfl_xor_sync(0xffffffffu, v, o);
    if ((threadIdx.x & 31) == 0 && v != 0) atomicOr(&g_flag[0], 1);
}

__global__ void convert_k(const int* __restrict__ ei_raw, const int* __restrict__ batch_raw) {
    bool is64 = (g_flag[0] == 0);
    int i = blockIdx.x * blockDim.x + threadIdx.x;
    if (i < NE) {
        if (is64) {
            g_src[i] = ei_raw[2 * i];
            g_dst[i] = ei_raw[2 * (NE + i)];
        } else {
            g_src[i] = ei_raw[i];
            g_dst[i] = ei_raw[NE + i];
        }
    }
    if (i < NN) {
        g_batch[i] = is64 ? batch_raw[2 * i] : batch_raw[i];
    }
}

// ---------------- zero kernels ----------------
__global__ void zero_conv_k() {  // zero g_agg and g_stats
    int i = blockIdx.x * blockDim.x + threadIdx.x;
    if (i < NN * D) g_agg[i] = 0.f;
    if (i < 2 * D) g_stats[i] = 0.f;
}
__global__ void zero_misc_k() {  // zero pool and flag
    int i = blockIdx.x * blockDim.x + threadIdx.x;
    if (i < NG * 4 * D) g_pool[i] = 0.f;
    if (i == 0) g_flag[0] = 0;
}

// ---------------- scatter-sum over edges ----------------
// 32 threads per edge; each thread handles one float4 of the 128-dim row.
__global__ void scatter_k(const float* __restrict__ X) {
    int t = blockIdx.x * blockDim.x + threadIdx.x;
    int e = t >> 5;
    if (e >= NE) return;
    int lane = t & 31;
    int s = g_src[e], d = g_dst[e];
    float4 v = reinterpret_cast<const float4*>(X)[s * 32 + lane];
    float* p = g_agg + (size_t)d * D + lane * 4;
    atomicAdd(p + 0, v.x);
    atomicAdd(p + 1, v.y);
    atomicAdd(p + 2, v.z);
    atomicAdd(p + 3, v.w);
}

// ---------------- fused SGEMM ----------------
// C[M,NC] = f(Aeff[M,K] @ B[K,NC] + bias), tiles: BM=64, BN=128, BK=16, 256 thr
// PRE: 0 = plain A; 1 = A + A2 (agg + x); 2 = relu(A*scale[k] + shift[k]) (BN)
template <int PRE, bool RELU>
__global__ __launch_bounds__(256) void gemm_k(
    const float* __restrict__ A, const float* __restrict__ A2,
    const float* __restrict__ B, const float* __restrict__ bias,
    float* __restrict__ C, int M, int K, int NC)
{
    __shared__ float As[16][65];
    __shared__ float Bs[16][128];

    int tid = threadIdx.x;
    int row0 = blockIdx.x * 64;
    int col0 = blockIdx.y * 128;
    int warp = tid >> 5, lane = tid & 31;
    int r0 = warp * 8;     // 8 rows per warp
    int c0 = lane * 4;     // 4 cols per lane

    float acc[8][4];
    #pragma unroll
    for (int i = 0; i < 8; i++)
        #pragma unroll
        for (int j = 0; j < 4; j++) acc[i][j] = 0.f;

    int ar = tid >> 2;          // 0..63 (A tile row)
    int ac = (tid & 3) * 4;     // 0,4,8,12 (A tile col group)
    int br = tid >> 5;          // 0..7 (B tile row base)
    int bc = (tid & 31) * 4;    // B tile col group

    for (int kk = 0; kk < K; kk += 16) {
        // ---- load A tile (with fused prologue) ----
        {
            int grow = row0 + ar;
            float4 v = make_float4(0.f, 0.f, 0.f, 0.f);
            if (grow < M) {
                v = *reinterpret_cast<const float4*>(A + (size_t)grow * K + kk + ac);
                if (PRE == 1) {
                    float4 w = *reinterpret_cast<const float4*>(A2 + (size_t)grow * K + kk + ac);
                    v.x += w.x; v.y += w.y; v.z += w.z; v.w += w.w;
                } else if (PRE == 2) {
                    float s0 = g_aff[kk + ac + 0], t0 = g_aff[D + kk + ac + 0];
                    float s1 = g_aff[kk + ac + 1], t1 = g_aff[D + kk + ac + 1];
                    float s2 = g_aff[kk + ac + 2], t2 = g_aff[D + kk + ac + 2];
                    float s3 = g_aff[kk + ac + 3], t3 = g_aff[D + kk + ac + 3];
                    v.x = fmaxf(fmaf(v.x, s0, t0), 0.f);
                    v.y = fmaxf(fmaf(v.y, s1, t1), 0.f);
                    v.z = fmaxf(fmaf(v.z, s2, t2), 0.f);
                    v.w = fmaxf(fmaf(v.w, s3, t3), 0.f);
                }
            }
            As[ac + 0][ar] = v.x;
            As[ac + 1][ar] = v.y;
            As[ac + 2][ar] = v.z;
            As[ac + 3][ar] = v.w;
        }
        // ---- load B tile ----
        #pragma unroll
        for (int i = 0; i < 2; i++) {
            int krow = br + i * 8;
            float4 v = *reinterpret_cast<const float4*>(B + (size_t)(kk + krow) * NC + col0 + bc);
            *reinterpret_cast<float4*>(&Bs[krow][bc]) = v;
        }
        __syncthreads();
        // ---- compute ----
        #pragma unroll
        for (int k = 0; k < 16; k++) {
            float4 bv = *reinterpret_cast<const float4*>(&Bs[k][c0]);
            #pragma unroll
            for (int i = 0; i < 8; i++) {
                float a = As[k][r0 + i];
                acc[i][0] = fmaf(a, bv.x, acc[i][0]);
                acc[i][1] = fmaf(a, bv.y, acc[i][1]);
                acc[i][2] = fmaf(a, bv.z, acc[i][2]);
                acc[i][3] = fmaf(a, bv.w, acc[i][3]);
            }
        }
        __syncthreads();
    }
    // ---- epilogue ----
    float4 bb = *reinterpret_cast<const float4*>(bias + col0 + c0);
    #pragma unroll
    for (int i = 0; i < 8; i++) {
        int grow = row0 + r0 + i;
        if (grow < M) {
            float4 o;
            o.x = acc[i][0] + bb.x;
            o.y = acc[i][1] + bb.y;
            o.z = acc[i][2] + bb.z;
            o.w = acc[i][3] + bb.w;
            if (RELU) {
                o.x = fmaxf(o.x, 0.f); o.y = fmaxf(o.y, 0.f);
                o.z = fmaxf(o.z, 0.f); o.w = fmaxf(o.w, 0.f);
            }
            *reinterpret_cast<float4*>(C + (size_t)grow * NC + col0 + c0) = o;
        }
    }
}

// ---------------- BN stats (column sum / sumsq over g_h) ----------------
__global__ void stats_k() {
    int c = threadIdx.x;  // 128 threads
    float s = 0.f, sq = 0.f;
    for (int r = blockIdx.x; r < NN; r += gridDim.x) {
        float v = g_h[(size_t)r * D + c];
        s += v;
        sq = fmaf(v, v, sq);
    }
    atomicAdd(&g_stats[c], s);
    atomicAdd(&g_stats[D + c], sq);
}

__global__ void bn_finalize_k(const float* __restrict__ gamma, const float* __restrict__ beta) {
    int c = threadIdx.x;
    float mu = g_stats[c] * (1.f / NN);
    float var = g_stats[D + c] * (1.f / NN) - mu * mu;
    float sc = gamma[c] * rsqrtf(var + BN_EPS);
    g_aff[c] = sc;
    g_aff[D + c] = beta[c] - mu * sc;
}

// ---------------- pooling: sum + max per graph ----------------
// concat layout: [a1(0:128) | a2(128:256) | m1(256:384) | m2(384:512)]
// post-ReLU values are >= 0, so int-compare atomicMax on float bits is exact,
// and 0-init matches the reference's empty-segment -> 0 rule.
__global__ void pool_k() {
    int t = blockIdx.x * blockDim.x + threadIdx.x;
    if (t >= NN * D) return;
    int n = t >> 7;
    int c = t & 127;
    int b = g_batch[n];
    float v1 = g_h1[t];
    float v2 = g_h2[t];
    float* base = g_pool + (size_t)b * (4 * D);
    atomicAdd(base + c, v1);
    atomicAdd(base + D + c, v2);
    atomicMax(reinterpret_cast<int*>(base + 2 * D + c), __float_as_int(v1));
    atomicMax(reinterpret_cast<int*>(base + 3 * D + c), __float_as_int(v2));
}

// ---------------- final dot + sigmoid ----------------
__global__ void readout2_k(const float* __restrict__ W2, const float* __restrict__ b2,
                           float* __restrict__ out, int out_size) {
    __shared__ float red[8];
    int g = blockIdx.x, tid = threadIdx.x;  // 256 threads
    const float* row = g_hidden + (size_t)g * 512;
    float s = fmaf(row[tid], W2[tid], row[256 + tid] * W2[256 + tid]);
    #pragma unroll
    for (int o = 16; o > 0; o >>= 1) s += __shfl_down_sync(0xffffffffu, s, o);
    if ((tid & 31) == 0) red[tid >> 5] = s;
    __syncthreads();
    if (tid < 8) {
        float t = red[tid];
        #pragma unroll
        for (int o = 4; o > 0; o >>= 1) t += __shfl_down_sync(0xffu, t, o);
        if (tid == 0) {
            float logit = t + b2[0];
            if (out_size >= NG) out[g] = 1.f / (1.f + expf(-logit));
            if (out_size >= 2 * NG) out[NG + g] = logit;
        }
    }
}

// ---------------- launch ----------------
extern "C" void kernel_launch(void* const* d_in, const int* in_sizes, int n_in,
                              void* d_out, int out_size) {
    const float* x       = (const float*)d_in[0];
    const int*   ei_raw  = (const int*)d_in[1];
    const int*   bat_raw = (const int*)d_in[2];
    const float* c1_W1 = (const float*)d_in[3];
    const float* c1_b1 = (const float*)d_in[4];
    const float* c1_g  = (const float*)d_in[5];
    const float* c1_be = (const float*)d_in[6];
    const float* c1_W2 = (const float*)d_in[7];
    const float* c1_b2 = (const float*)d_in[8];
    const float* c2_W1 = (const float*)d_in[9];
    const float* c2_b1 = (const float*)d_in[10];
    const float* c2_g  = (const float*)d_in[11];
    const float* c2_be = (const float*)d_in[12];
    const float* c2_W2 = (const float*)d_in[13];
    const float* c2_b2 = (const float*)d_in[14];
    const float* lin1_W = (const float*)d_in[15];
    const float* lin1_b = (const float*)d_in[16];
    const float* lin2_W = (const float*)d_in[17];
    const float* lin2_b = (const float*)d_in[18];

    float *agg, *h, *h1, *h2, *pool, *hidden;
    cudaGetSymbolAddress((void**)&agg, g_agg);
    cudaGetSymbolAddress((void**)&h, g_h);
    cudaGetSymbolAddress((void**)&h1, g_h1);
    cudaGetSymbolAddress((void**)&h2, g_h2);
    cudaGetSymbolAddress((void**)&pool, g_pool);
    cudaGetSymbolAddress((void**)&hidden, g_hidden);

    const int nconv_blk = (NN * D + 255) / 256;
    const int scat_blk = (NE * 32 + 255) / 256;
    dim3 gemm_node((NN + 63) / 64, 1);
    dim3 gemm_read((NG + 63) / 64, 4);

    // dtype detect + index conversion
    zero_misc_k<<<(NG * 4 * D + 255) / 256, 256>>>();
    detect_k<<<64, 256>>>(ei_raw);
    convert_k<<<(NE + 255) / 256, 256>>>(ei_raw, bat_raw);

    // ---- conv1 ----
    zero_conv_k<<<nconv_blk, 256>>>();
    scatter_k<<<scat_blk, 256>>>(x);
    gemm_k<1, false><<<gemm_node, 256>>>(agg, x, c1_W1, c1_b1, h, NN, D, D);
    stats_k<<<256, 128>>>();
    bn_finalize_k<<<1, 128>>>(c1_g, c1_be);
    gemm_k<2, true><<<gemm_node, 256>>>(h, nullptr, c1_W2, c1_b2, h1, NN, D, D);

    // ---- conv2 ----
    zero_conv_k<<<nconv_blk, 256>>>();
    scatter_k<<<scat_blk, 256>>>(h1);
    gemm_k<1, false><<<gemm_node, 256>>>(agg, h1, c2_W1, c2_b1, h, NN, D, D);
    stats_k<<<256, 128>>>();
    bn_finalize_k<<<1, 128>>>(c2_g, c2_be);
    gemm_k<2, true><<<gemm_node, 256>>>(h, nullptr, c2_W2, c2_b2, h2, NN, D, D);

    // ---- pooling + readout ----
    pool_k<<<nconv_blk, 256>>>();
    gemm_k<0, true><<<gemm_read, 256>>>(pool, nullptr, lin1_W, lin1_b, hidden, NG, 4 * D, 4 * D);
    readout2_k<<<NG, 256>>>(lin2_W, lin2_b, (float*)d_out, out_size);
}

// round 2
// speedup vs baseline: 1.4010x; 1.4010x over previous
#include <cuda_runtime.h>
#include <math.h>

#define NN 50000
#define NE 600000
#define D  128
#define NG 512
#define BN_EPS 1e-5f

// ---------------- scratch (device globals; no allocations) ----------------
__device__ float g_agg[NN * D];      // gather output: sum(neigh) + x
__device__ float g_h[NN * D];        // pre-BN linear output
__device__ float g_h1[NN * D];       // conv1 output
__device__ float g_h2[NN * D];       // conv2 output
__device__ float g_stats[2 * D];     // sum, sumsq
__device__ float g_aff[2 * D];       // scale, shift
__device__ float g_pool[NG * 4 * D]; // [a1 | a2 | m1 | m2]
__device__ float g_hidden[NG * 4 * D];
__device__ int   g_src[NE];
__device__ int   g_dst[NE];
__device__ int   g_adj[NE];          // CSR adjacency (src ids grouped by dst)
__device__ int   g_batch[NN];
__device__ int   g_deg[NN];
__device__ int   g_off[NN + 1];
__device__ int   g_cur[NN];
__device__ int   g_flag[1];

// ---------------- zero everything that needs it ----------------
__global__ void zero_all_k() {
    int i = blockIdx.x * blockDim.x + threadIdx.x;  // 262144 threads
    if (i < NG * 4 * D) { g_pool[i] = 0.f; g_hidden[i] = 0.f; }
    if (i < NN) g_deg[i] = 0;
    if (i < 2 * D) g_stats[i] = 0.f;
    if (i == 0) g_flag[0] = 0;
}

// ---------------- dtype detect ----------------
// int64 edge_index: hi-words (odd 32-bit words of the src half) are all zero.
__global__ void detect_k(const int* __restrict__ w) {
    int tid = blockIdx.x * blockDim.x + threadIdx.x;
    int stride = gridDim.x * blockDim.x;
    int v = 0;
    for (int i = tid; i < NE; i += stride) v |= w[2 * i + 1];
    #pragma unroll
    for (int o = 16; o > 0; o >>= 1) v |= __shfl_xor_sync(0xffffffffu, v, o);
    if ((threadIdx.x & 31) == 0 && v != 0) atomicOr(&g_flag[0], 1);
}

// convert indices + histogram degrees (fused)
__global__ void convert_hist_k(const int* __restrict__ ei_raw, const int* __restrict__ batch_raw) {
    bool is64 = (g_flag[0] == 0);
    int i = blockIdx.x * blockDim.x + threadIdx.x;
    if (i < NE) {
        int s, d;
        if (is64) { s = ei_raw[2 * i]; d = ei_raw[2 * (NE + i)]; }
        else      { s = ei_raw[i];     d = ei_raw[NE + i]; }
        g_src[i] = s;
        g_dst[i] = d;
        atomicAdd(&g_deg[d], 1);
    }
    if (i < NN) g_batch[i] = is64 ? batch_raw[2 * i] : batch_raw[i];
}

// single-block exclusive scan over degrees -> offsets (+cursor copy)
__global__ void scan_k() {
    __shared__ int s[1024];
    const int CH = (NN + 1023) / 1024;  // 49
    int t = threadIdx.x;
    int beg = t * CH;
    int end = beg + CH; if (end > NN) end = NN;
    int sum = 0;
    for (int i = beg; i < end; i++) sum += g_deg[i];
    s[t] = sum;
    __syncthreads();
    // Hillis-Steele inclusive scan
    for (int o = 1; o < 1024; o <<= 1) {
        int v = (t >= o) ? s[t - o] : 0;
        __syncthreads();
        s[t] += v;
        __syncthreads();
    }
    int run = s[t] - sum;  // exclusive prefix
    for (int i = beg; i < end; i++) {
        g_off[i] = run;
        g_cur[i] = run;
        run += g_deg[i];
    }
    if (t == 1023) g_off[NN] = NE;
}

__global__ void fill_k() {
    int i = blockIdx.x * blockDim.x + threadIdx.x;
    if (i >= NE) return;
    int pos = atomicAdd(&g_cur[g_dst[i]], 1);
    g_adj[pos] = g_src[i];
}

// ---------------- gather aggregation: agg = x + sum_{in-edges} X[src] ----------------
// one warp per node; lane l handles float4 #l of the 128-dim row
__global__ void gather_k(const float* __restrict__ X) {
    int w = (blockIdx.x * blockDim.x + threadIdx.x) >> 5;
    if (w >= NN) return;
    int lane = threadIdx.x & 31;
    int beg = g_off[w], end = g_off[w + 1];
    const float4* X4 = reinterpret_cast<const float4*>(X);
    float4 acc = X4[(size_t)w * 32 + lane];
    int j = beg;
    for (; j + 1 < end; j += 2) {
        int s0 = g_adj[j], s1 = g_adj[j + 1];
        float4 v0 = X4[(size_t)s0 * 32 + lane];
        float4 v1 = X4[(size_t)s1 * 32 + lane];
        acc.x += v0.x; acc.y += v0.y; acc.z += v0.z; acc.w += v0.w;
        acc.x += v1.x; acc.y += v1.y; acc.z += v1.z; acc.w += v1.w;
    }
    if (j < end) {
        int s0 = g_adj[j];
        float4 v0 = X4[(size_t)s0 * 32 + lane];
        acc.x += v0.x; acc.y += v0.y; acc.z += v0.z; acc.w += v0.w;
    }
    reinterpret_cast<float4*>(g_agg)[(size_t)w * 32 + lane] = acc;
}

// ---------------- fused SGEMM ----------------
// C[M,NC] = f(Aeff @ B + bias); BM=128, BN=128, BK=8, 256 threads, 8x8 microtile
// PRE: 0 = plain A; 2 = relu(A*scale[k] + shift[k]) (fused BN+ReLU on A-load)
// ATOMIC: split-K accumulation via atomicAdd (no bias/relu here)
template <int PRE, bool RELU, bool ATOMIC>
__global__ __launch_bounds__(256) void gemm_k(
    const float* __restrict__ A, const float* __restrict__ B,
    const float* __restrict__ bias, float* __restrict__ C,
    int M, int lda, int NC, int Klen)
{
    __shared__ float As[8][132];
    __shared__ float Bs[8][128];

    int tid = threadIdx.x;
    int row0 = blockIdx.x * 128;
    int col0 = blockIdx.y * 128;
    int k0 = blockIdx.z * Klen;

    int ar = tid >> 1;            // A tile row 0..127
    int aseg = (tid & 1) * 4;     // A k-seg 0 or 4
    int bk = tid >> 5;            // B tile k-row 0..7
    int bc = (tid & 31) * 4;      // B tile col group
    int ty = tid >> 4;            // 0..15
    int tx = tid & 15;            // 0..15

    float acc[8][8];
    #pragma unroll
    for (int i = 0; i < 8; i++)
        #pragma unroll
        for (int j = 0; j < 8; j++) acc[i][j] = 0.f;

    for (int kk = 0; kk < Klen; kk += 8) {
        // ---- A tile (with fused BN prologue) ----
        {
            int grow = row0 + ar;
            float4 v = make_float4(0.f, 0.f, 0.f, 0.f);
            if (grow < M) {
                int kc = k0 + kk + aseg;
                v = *reinterpret_cast<const float4*>(A + (size_t)grow * lda + kc);
                if (PRE == 2) {
                    float s0 = g_aff[kc + 0], t0 = g_aff[D + kc + 0];
                    float s1 = g_aff[kc + 1], t1 = g_aff[D + kc + 1];
                    float s2 = g_aff[kc + 2], t2 = g_aff[D + kc + 2];
                    float s3 = g_aff[kc + 3], t3 = g_aff[D + kc + 3];
                    v.x = fmaxf(fmaf(v.x, s0, t0), 0.f);
                    v.y = fmaxf(fmaf(v.y, s1, t1), 0.f);
                    v.z = fmaxf(fmaf(v.z, s2, t2), 0.f);
                    v.w = fmaxf(fmaf(v.w, s3, t3), 0.f);
                }
            }
            As[aseg + 0][ar] = v.x;
            As[aseg + 1][ar] = v.y;
            As[aseg + 2][ar] = v.z;
            As[aseg + 3][ar] = v.w;
        }
        // ---- B tile ----
        {
            float4 v = *reinterpret_cast<const float4*>(B + (size_t)(k0 + kk + bk) * NC + col0 + bc);
            *reinterpret_cast<float4*>(&Bs[bk][bc]) = v;
        }
        __syncthreads();
        // ---- compute ----
        #pragma unroll
        for (int k = 0; k < 8; k++) {
            float4 a0 = *reinterpret_cast<const float4*>(&As[k][ty * 4]);
            float4 a1 = *reinterpret_cast<const float4*>(&As[k][ty * 4 + 64]);
            float4 b0 = *reinterpret_cast<const float4*>(&Bs[k][tx * 4]);
            float4 b1 = *reinterpret_cast<const float4*>(&Bs[k][tx * 4 + 64]);
            float av[8] = {a0.x, a0.y, a0.z, a0.w, a1.x, a1.y, a1.z, a1.w};
            float bv[8] = {b0.x, b0.y, b0.z, b0.w, b1.x, b1.y, b1.z, b1.w};
            #pragma unroll
            for (int i = 0; i < 8; i++)
                #pragma unroll
                for (int j = 0; j < 8; j++)
                    acc[i][j] = fmaf(av[i], bv[j], acc[i][j]);
        }
        __syncthreads();
    }

    // ---- epilogue ----
    if (ATOMIC) {
        #pragma unroll
        for (int i = 0; i < 8; i++) {
            int grow = row0 + ty * 4 + (i < 4 ? i : 60 + i);
            if (grow < M) {
                #pragma unroll
                for (int j = 0; j < 8; j++) {
                    int gcol = col0 + tx * 4 + (j < 4 ? j : 60 + j);
                    atomicAdd(&C[(size_t)grow * NC + gcol], acc[i][j]);
                }
            }
        }
    } else {
        float4 bb0 = *reinterpret_cast<const float4*>(bias + col0 + tx * 4);
        float4 bb1 = *reinterpret_cast<const float4*>(bias + col0 + tx * 4 + 64);
        #pragma unroll
        for (int i = 0; i < 8; i++) {
            int grow = row0 + ty * 4 + (i < 4 ? i : 60 + i);
            if (grow < M) {
                float4 o0, o1;
                o0.x = acc[i][0] + bb0.x; o0.y = acc[i][1] + bb0.y;
                o0.z = acc[i][2] + bb0.z; o0.w = acc[i][3] + bb0.w;
                o1.x = acc[i][4] + bb1.x; o1.y = acc[i][5] + bb1.y;
                o1.z = acc[i][6] + bb1.z; o1.w = acc[i][7] + bb1.w;
                if (RELU) {
                    o0.x = fmaxf(o0.x, 0.f); o0.y = fmaxf(o0.y, 0.f);
                    o0.z = fmaxf(o0.z, 0.f); o0.w = fmaxf(o0.w, 0.f);
                    o1.x = fmaxf(o1.x, 0.f); o1.y = fmaxf(o1.y, 0.f);
                    o1.z = fmaxf(o1.z, 0.f); o1.w = fmaxf(o1.w, 0.f);
                }
                *reinterpret_cast<float4*>(C + (size_t)grow * NC + col0 + tx * 4) = o0;
                *reinterpret_cast<float4*>(C + (size_t)grow * NC + col0 + tx * 4 + 64) = o1;
            }
        }
    }
}

// ---------------- BN stats (column sum / sumsq over g_h) ----------------
__global__ void stats_k() {
    int c = threadIdx.x;  // 128 threads
    float s = 0.f, sq = 0.f;
    for (int r = blockIdx.x; r < NN; r += gridDim.x) {
        float v = g_h[(size_t)r * D + c];
        s += v;
        sq = fmaf(v, v, sq);
    }
    atomicAdd(&g_stats[c], s);
    atomicAdd(&g_stats[D + c], sq);
}

__global__ void bn_finalize_k(const float* __restrict__ gamma, const float* __restrict__ beta) {
    int c = threadIdx.x;
    float mu = g_stats[c] * (1.f / NN);
    float var = g_stats[D + c] * (1.f / NN) - mu * mu;
    float sc = gamma[c] * rsqrtf(var + BN_EPS);
    g_aff[c] = sc;
    g_aff[D + c] = beta[c] - mu * sc;
    g_stats[c] = 0.f;       // reset for next layer
    g_stats[D + c] = 0.f;
}

// ---------------- pooling: sum + max per graph ----------------
__global__ void pool_k() {
    int t = blockIdx.x * blockDim.x + threadIdx.x;
    if (t >= NN * D) return;
    int n = t >> 7;
    int c = t & 127;
    int b = g_batch[n];
    float v1 = g_h1[t];
    float v2 = g_h2[t];
    float* base = g_pool + (size_t)b * (4 * D);
    atomicAdd(base + c, v1);
    atomicAdd(base + D + c, v2);
    atomicMax(reinterpret_cast<int*>(base + 2 * D + c), __float_as_int(v1));
    atomicMax(reinterpret_cast<int*>(base + 3 * D + c), __float_as_int(v2));
}

// ---------------- final: relu(hidden + b1) . W2 + b2 -> sigmoid ----------------
__global__ void readout2_k(const float* __restrict__ b1, const float* __restrict__ W2,
                           const float* __restrict__ b2,
                           float* __restrict__ out, int out_size) {
    __shared__ float red[8];
    int g = blockIdx.x, tid = threadIdx.x;  // 256 threads
    const float* row = g_hidden + (size_t)g * 512;
    float v0 = fmaxf(row[tid] + b1[tid], 0.f) * W2[tid];
    float v1 = fmaxf(row[256 + tid] + b1[256 + tid], 0.f) * W2[256 + tid];
    float s = v0 + v1;
    #pragma unroll
    for (int o = 16; o > 0; o >>= 1) s += __shfl_down_sync(0xffffffffu, s, o);
    if ((tid & 31) == 0) red[tid >> 5] = s;
    __syncthreads();
    if (tid < 8) {
        float t = red[tid];
        #pragma unroll
        for (int o = 4; o > 0; o >>= 1) t += __shfl_down_sync(0xffu, t, o);
        if (tid == 0) {
            float logit = t + b2[0];
            if (out_size >= NG) out[g] = 1.f / (1.f + expf(-logit));
            if (out_size >= 2 * NG) out[NG + g] = logit;
        }
    }
}

// ---------------- launch ----------------
extern "C" void kernel_launch(void* const* d_in, const int* in_sizes, int n_in,
                              void* d_out, int out_size) {
    const float* x       = (const float*)d_in[0];
    const int*   ei_raw  = (const int*)d_in[1];
    const int*   bat_raw = (const int*)d_in[2];
    const float* c1_W1 = (const float*)d_in[3];
    const float* c1_b1 = (const float*)d_in[4];
    const float* c1_g  = (const float*)d_in[5];
    const float* c1_be = (const float*)d_in[6];
    const float* c1_W2 = (const float*)d_in[7];
    const float* c1_b2 = (const float*)d_in[8];
    const float* c2_W1 = (const float*)d_in[9];
    const float* c2_b1 = (const float*)d_in[10];
    const float* c2_g  = (const float*)d_in[11];
    const float* c2_be = (const float*)d_in[12];
    const float* c2_W2 = (const float*)d_in[13];
    const float* c2_b2 = (const float*)d_in[14];
    const float* lin1_W = (const float*)d_in[15];
    const float* lin1_b = (const float*)d_in[16];
    const float* lin2_W = (const float*)d_in[17];
    const float* lin2_b = (const float*)d_in[18];

    float *agg, *h, *h1, *h2, *pool, *hidden;
    cudaGetSymbolAddress((void**)&agg, g_agg);
    cudaGetSymbolAddress((void**)&h, g_h);
    cudaGetSymbolAddress((void**)&h1, g_h1);
    cudaGetSymbolAddress((void**)&h2, g_h2);
    cudaGetSymbolAddress((void**)&pool, g_pool);
    cudaGetSymbolAddress((void**)&hidden, g_hidden);

    dim3 gemm_node((NN + 127) / 128, 1, 1);     // 391 blocks
    dim3 gemm_read(4, 4, 8);                    // 128 blocks, split-K=8 (Klen=64)
    const int gat_blk = (NN * 32 + 255) / 256;  // 6250
    const int edge_blk = (NE + 255) / 256;

    // ---- prep: detect dtype, convert, build CSR ----
    zero_all_k<<<1024, 256>>>();
    detect_k<<<64, 256>>>(ei_raw);
    convert_hist_k<<<edge_blk, 256>>>(ei_raw, bat_raw);
    scan_k<<<1, 1024>>>();
    fill_k<<<edge_blk, 256>>>();

    // ---- conv1 ----
    gather_k<<<gat_blk, 256>>>(x);
    gemm_k<0, false, false><<<gemm_node, 256>>>(agg, c1_W1, c1_b1, h, NN, D, D, D);
    stats_k<<<256, 128>>>();
    bn_finalize_k<<<1, 128>>>(c1_g, c1_be);
    gemm_k<2, true, false><<<gemm_node, 256>>>(h, c1_W2, c1_b2, h1, NN, D, D, D);

    // ---- conv2 ----
    gather_k<<<gat_blk, 256>>>(h1);
    gemm_k<0, false, false><<<gemm_node, 256>>>(agg, c2_W1, c2_b1, h, NN, D, D, D);
    stats_k<<<256, 128>>>();
    bn_finalize_k<<<1, 128>>>(c2_g, c2_be);
    gemm_k<2, true, false><<<gemm_node, 256>>>(h, c2_W2, c2_b2, h2, NN, D, D, D);

    // ---- pooling + readout ----
    pool_k<<<(NN * D + 255) / 256, 256>>>();
    gemm_k<0, false, true><<<gemm_read, 256>>>(pool, lin1_W, nullptr, hidden, NG, 4 * D, 4 * D, 64);
    readout2_k<<<NG, 256>>>(lin1_b, lin2_W, lin2_b, (float*)d_out, out_size);
}

// round 3
// speedup vs baseline: 1.7396x; 1.2416x over previous
#include <cuda_runtime.h>
#include <math.h>

#define NN 50000
#define NE 600000
#define D  128
#define NG 512
#define BN_EPS 1e-5f
#define NBLK 196   // ceil(NN/256)

// ---------------- scratch (device globals; no allocations) ----------------
__device__ float g_agg[NN * D];      // gather output: sum(neigh) + x
__device__ float g_h[NN * D];        // pre-BN linear output
__device__ float g_h1[NN * D];       // conv1 output
__device__ float g_stats[2 * D];     // sum, sumsq
__device__ float g_aff[2 * D];       // scale, shift
__device__ float g_pool[NG * 4 * D]; // [a1 | a2 | m1 | m2]
__device__ float g_hidden[NG * 4 * D];
__device__ int   g_src[NE];
__device__ int   g_dst[NE];
__device__ int   g_adj[NE];          // CSR adjacency (src ids grouped by dst)
__device__ int   g_batch[NN];
__device__ int   g_deg[NN];
__device__ int   g_off[NN + 1];
__device__ int   g_cur[NN];
__device__ int   g_bsum[256];
__device__ int   g_boff[256];
__device__ int   g_flag[1];

// ---------------- zero everything that needs it ----------------
__global__ void zero_all_k() {
    int i = blockIdx.x * blockDim.x + threadIdx.x;
    if (i < NG * 4 * D) { g_pool[i] = 0.f; g_hidden[i] = 0.f; }
    if (i < NN) g_deg[i] = 0;
    if (i < 2 * D) g_stats[i] = 0.f;
    if (i == 0) g_flag[0] = 0;
}

// ---------------- dtype detect ----------------
__global__ void detect_k(const int* __restrict__ w) {
    int tid = blockIdx.x * blockDim.x + threadIdx.x;
    int stride = gridDim.x * blockDim.x;
    int v = 0;
    for (int i = tid; i < NE; i += stride) v |= w[2 * i + 1];
    #pragma unroll
    for (int o = 16; o > 0; o >>= 1) v |= __shfl_xor_sync(0xffffffffu, v, o);
    if ((threadIdx.x & 31) == 0 && v != 0) atomicOr(&g_flag[0], 1);
}

// convert indices + histogram degrees (fused)
__global__ void convert_hist_k(const int* __restrict__ ei_raw, const int* __restrict__ batch_raw) {
    bool is64 = (g_flag[0] == 0);
    int i = blockIdx.x * blockDim.x + threadIdx.x;
    if (i < NE) {
        int s, d;
        if (is64) { s = ei_raw[2 * i]; d = ei_raw[2 * (NE + i)]; }
        else      { s = ei_raw[i];     d = ei_raw[NE + i]; }
        g_src[i] = s;
        g_dst[i] = d;
        atomicAdd(&g_deg[d], 1);
    }
    if (i < NN) g_batch[i] = is64 ? batch_raw[2 * i] : batch_raw[i];
}

// ---------------- 3-phase parallel scan (replaces 82us 1-block scan) ----------------
__global__ void bsum_k() {
    __shared__ int s[256];
    int t = threadIdx.x;
    int i = blockIdx.x * 256 + t;
    int v = (i < NN) ? g_deg[i] : 0;
    s[t] = v;
    __syncthreads();
    for (int o = 128; o > 0; o >>= 1) {
        if (t < o) s[t] += s[t + o];
        __syncthreads();
    }
    if (t == 0) g_bsum[blockIdx.x] = s[0];
}

__global__ void bscan_k() {
    __shared__ int s[256];
    int t = threadIdx.x;
    int v = (t < NBLK) ? g_bsum[t] : 0;
    s[t] = v;
    __syncthreads();
    for (int o = 1; o < 256; o <<= 1) {
        int u = (t >= o) ? s[t - o] : 0;
        __syncthreads();
        s[t] += u;
        __syncthreads();
    }
    g_boff[t] = s[t] - v;  // exclusive
}

__global__ void offsets_k() {
    __shared__ int s[256];
    int t = threadIdx.x;
    int i = blockIdx.x * 256 + t;
    int v = (i < NN) ? g_deg[i] : 0;
    s[t] = v;
    __syncthreads();
    for (int o = 1; o < 256; o <<= 1) {
        int u = (t >= o) ? s[t - o] : 0;
        __syncthreads();
        s[t] += u;
        __syncthreads();
    }
    int off = g_boff[blockIdx.x] + s[t] - v;
    if (i < NN) { g_off[i] = off; g_cur[i] = off; }
    if (blockIdx.x == NBLK - 1 && t == 255) g_off[NN] = NE;
}

__global__ void fill_k() {
    int i = blockIdx.x * blockDim.x + threadIdx.x;
    if (i >= NE) return;
    int pos = atomicAdd(&g_cur[g_dst[i]], 1);
    g_adj[pos] = g_src[i];
}

// ---------------- gather aggregation: agg = x + sum_{in-edges} X[src] ----------------
__global__ void gather_k(const float* __restrict__ X) {
    int w = (blockIdx.x * blockDim.x + threadIdx.x) >> 5;
    if (w >= NN) return;
    int lane = threadIdx.x & 31;
    int beg = g_off[w], end = g_off[w + 1];
    const float4* X4 = reinterpret_cast<const float4*>(X);
    float4 acc = X4[(size_t)w * 32 + lane];
    int j = beg;
    for (; j + 1 < end; j += 2) {
        int s0 = g_adj[j], s1 = g_adj[j + 1];
        float4 v0 = X4[(size_t)s0 * 32 + lane];
        float4 v1 = X4[(size_t)s1 * 32 + lane];
        acc.x += v0.x; acc.y += v0.y; acc.z += v0.z; acc.w += v0.w;
        acc.x += v1.x; acc.y += v1.y; acc.z += v1.z; acc.w += v1.w;
    }
    if (j < end) {
        int s0 = g_adj[j];
        float4 v0 = X4[(size_t)s0 * 32 + lane];
        acc.x += v0.x; acc.y += v0.y; acc.z += v0.z; acc.w += v0.w;
    }
    reinterpret_cast<float4*>(g_agg)[(size_t)w * 32 + lane] = acc;
}

// ---------------- fused SGEMM ----------------
// C = f(Aeff @ B + bias); BM=128, BN=128, BK=8, 256 thr, 8x8 microtile
// PRE:   0 plain A; 2 relu(A*scale+shift) fused BN
// STATS: accumulate column sum/sumsq of output into g_stats (pre-ReLU GEMM1)
// POOL:  -1 none; 0/1 -> fused graph sum/max pooling for layer POOL+1
// STORE: write C (false for layer-2 GEMM2 whose only consumer is pooling)
template <int PRE, bool RELU, bool ATOMIC, bool STATS, int POOL, bool STORE>
__global__ __launch_bounds__(256) void gemm_k(
    const float* __restrict__ A, const float* __restrict__ B,
    const float* __restrict__ bias, float* __restrict__ C,
    int M, int lda, int NC, int Klen)
{
    __shared__ float As[8][132];
    __shared__ float Bs[8][128];

    int tid = threadIdx.x;
    int row0 = blockIdx.x * 128;
    int col0 = blockIdx.y * 128;
    int k0 = blockIdx.z * Klen;

    int ar = tid >> 1;
    int aseg = (tid & 1) * 4;
    int bk = tid >> 5;
    int bc = (tid & 31) * 4;
    int ty = tid >> 4;
    int tx = tid & 15;

    float acc[8][8];
    #pragma unroll
    for (int i = 0; i < 8; i++)
        #pragma unroll
        for (int j = 0; j < 8; j++) acc[i][j] = 0.f;

    for (int kk = 0; kk < Klen; kk += 8) {
        {
            int grow = row0 + ar;
            float4 v = make_float4(0.f, 0.f, 0.f, 0.f);
            if (grow < M) {
                int kc = k0 + kk + aseg;
                v = *reinterpret_cast<const float4*>(A + (size_t)grow * lda + kc);
                if (PRE == 2) {
                    float s0 = g_aff[kc + 0], t0 = g_aff[D + kc + 0];
                    float s1 = g_aff[kc + 1], t1 = g_aff[D + kc + 1];
                    float s2 = g_aff[kc + 2], t2 = g_aff[D + kc + 2];
                    float s3 = g_aff[kc + 3], t3 = g_aff[D + kc + 3];
                    v.x = fmaxf(fmaf(v.x, s0, t0), 0.f);
                    v.y = fmaxf(fmaf(v.y, s1, t1), 0.f);
                    v.z = fmaxf(fmaf(v.z, s2, t2), 0.f);
                    v.w = fmaxf(fmaf(v.w, s3, t3), 0.f);
                }
            }
            As[aseg + 0][ar] = v.x;
            As[aseg + 1][ar] = v.y;
            As[aseg + 2][ar] = v.z;
            As[aseg + 3][ar] = v.w;
        }
        {
            float4 v = *reinterpret_cast<const float4*>(B + (size_t)(k0 + kk + bk) * NC + col0 + bc);
            *reinterpret_cast<float4*>(&Bs[bk][bc]) = v;
        }
        __syncthreads();
        #pragma unroll
        for (int k = 0; k < 8; k++) {
            float4 a0 = *reinterpret_cast<const float4*>(&As[k][ty * 4]);
            float4 a1 = *reinterpret_cast<const float4*>(&As[k][ty * 4 + 64]);
            float4 b0 = *reinterpret_cast<const float4*>(&Bs[k][tx * 4]);
            float4 b1 = *reinterpret_cast<const float4*>(&Bs[k][tx * 4 + 64]);
            float av[8] = {a0.x, a0.y, a0.z, a0.w, a1.x, a1.y, a1.z, a1.w};
            float bv[8] = {b0.x, b0.y, b0.z, b0.w, b1.x, b1.y, b1.z, b1.w};
            #pragma unroll
            for (int i = 0; i < 8; i++)
                #pragma unroll
                for (int j = 0; j < 8; j++)
                    acc[i][j] = fmaf(av[i], bv[j], acc[i][j]);
        }
        __syncthreads();
    }

    // ---- epilogue ----
    if (ATOMIC) {
        #pragma unroll
        for (int i = 0; i < 8; i++) {
            int grow = row0 + ty * 4 + (i < 4 ? i : 60 + i);
            if (grow < M) {
                #pragma unroll
                for (int j = 0; j < 8; j++) {
                    int gcol = col0 + tx * 4 + (j < 4 ? j : 60 + j);
                    atomicAdd(&C[(size_t)grow * NC + gcol], acc[i][j]);
                }
            }
        }
    } else {
        float4 bb0 = *reinterpret_cast<const float4*>(bias + col0 + tx * 4);
        float4 bb1 = *reinterpret_cast<const float4*>(bias + col0 + tx * 4 + 64);
        float csum[8], csq[8];
        if (STATS) {
            #pragma unroll
            for (int j = 0; j < 8; j++) { csum[j] = 0.f; csq[j] = 0.f; }
        }
        #pragma unroll
        for (int i = 0; i < 8; i++) {
            int grow = row0 + ty * 4 + (i < 4 ? i : 60 + i);
            if (grow < M) {
                float o[8];
                o[0] = acc[i][0] + bb0.x; o[1] = acc[i][1] + bb0.y;
                o[2] = acc[i][2] + bb0.z; o[3] = acc[i][3] + bb0.w;
                o[4] = acc[i][4] + bb1.x; o[5] = acc[i][5] + bb1.y;
                o[6] = acc[i][6] + bb1.z; o[7] = acc[i][7] + bb1.w;
                if (RELU) {
                    #pragma unroll
                    for (int j = 0; j < 8; j++) o[j] = fmaxf(o[j], 0.f);
                }
                if (STATS) {
                    #pragma unroll
                    for (int j = 0; j < 8; j++) {
                        csum[j] += o[j];
                        csq[j] = fmaf(o[j], o[j], csq[j]);
                    }
                }
                if (STORE) {
                    float4 o0 = make_float4(o[0], o[1], o[2], o[3]);
                    float4 o1 = make_float4(o[4], o[5], o[6], o[7]);
                    *reinterpret_cast<float4*>(C + (size_t)grow * NC + col0 + tx * 4) = o0;
                    *reinterpret_cast<float4*>(C + (size_t)grow * NC + col0 + tx * 4 + 64) = o1;
                }
                if (POOL >= 0) {
                    int b = g_batch[grow];
                    float* sb = g_pool + (size_t)b * (4 * D) + POOL * D + tx * 4;
                    int*   mb = reinterpret_cast<int*>(g_pool + (size_t)b * (4 * D) + (2 + POOL) * D + tx * 4);
                    #pragma unroll
                    for (int j = 0; j < 4; j++) {
                        atomicAdd(sb + j, o[j]);
                        atomicAdd(sb + 64 + j, o[4 + j]);
                        atomicMax(mb + j, __float_as_int(o[j]));
                        atomicMax(mb + 64 + j, __float_as_int(o[4 + j]));
                    }
                }
            }
        }
        if (STATS) {
            float* sred = &As[0][0];  // 256 floats (smem reuse, safe after last sync)
            sred[tid] = 0.f;
            __syncthreads();
            #pragma unroll
            for (int j = 0; j < 8; j++) {
                int c = tx * 4 + (j < 4 ? j : 60 + j);
                atomicAdd(&sred[c], csum[j]);
                atomicAdd(&sred[128 + c], csq[j]);
            }
            __syncthreads();
            atomicAdd(&g_stats[tid], sred[tid]);
        }
    }
}

__global__ void bn_finalize_k(const float* __restrict__ gamma, const float* __restrict__ beta) {
    int c = threadIdx.x;
    float mu = g_stats[c] * (1.f / NN);
    float var = g_stats[D + c] * (1.f / NN) - mu * mu;
    float sc = gamma[c] * rsqrtf(var + BN_EPS);
    g_aff[c] = sc;
    g_aff[D + c] = beta[c] - mu * sc;
    g_stats[c] = 0.f;   // reset for next layer
    g_stats[D + c] = 0.f;
}

// ---------------- final: relu(hidden + b1) . W2 + b2 -> sigmoid ----------------
__global__ void readout2_k(const float* __restrict__ b1, const float* __restrict__ W2,
                           const float* __restrict__ b2,
                           float* __restrict__ out, int out_size) {
    __shared__ float red[8];
    int g = blockIdx.x, tid = threadIdx.x;  // 256 threads
    const float* row = g_hidden + (size_t)g * 512;
    float v0 = fmaxf(row[tid] + b1[tid], 0.f) * W2[tid];
    float v1 = fmaxf(row[256 + tid] + b1[256 + tid], 0.f) * W2[256 + tid];
    float s = v0 + v1;
    #pragma unroll
    for (int o = 16; o > 0; o >>= 1) s += __shfl_down_sync(0xffffffffu, s, o);
    if ((tid & 31) == 0) red[tid >> 5] = s;
    __syncthreads();
    if (tid < 8) {
        float t = red[tid];
        #pragma unroll
        for (int o = 4; o > 0; o >>= 1) t += __shfl_down_sync(0xffu, t, o);
        if (tid == 0) {
            float logit = t + b2[0];
            if (out_size >= NG) out[g] = 1.f / (1.f + expf(-logit));
            if (out_size >= 2 * NG) out[NG + g] = logit;
        }
    }
}

// ---------------- launch ----------------
extern "C" void kernel_launch(void* const* d_in, const int* in_sizes, int n_in,
                              void* d_out, int out_size) {
    const float* x       = (const float*)d_in[0];
    const int*   ei_raw  = (const int*)d_in[1];
    const int*   bat_raw = (const int*)d_in[2];
    const float* c1_W1 = (const float*)d_in[3];
    const float* c1_b1 = (const float*)d_in[4];
    const float* c1_g  = (const float*)d_in[5];
    const float* c1_be = (const float*)d_in[6];
    const float* c1_W2 = (const float*)d_in[7];
    const float* c1_b2 = (const float*)d_in[8];
    const float* c2_W1 = (const float*)d_in[9];
    const float* c2_b1 = (const float*)d_in[10];
    const float* c2_g  = (const float*)d_in[11];
    const float* c2_be = (const float*)d_in[12];
    const float* c2_W2 = (const float*)d_in[13];
    const float* c2_b2 = (const float*)d_in[14];
    const float* lin1_W = (const float*)d_in[15];
    const float* lin1_b = (const float*)d_in[16];
    const float* lin2_W = (const float*)d_in[17];
    const float* lin2_b = (const float*)d_in[18];

    float *agg, *h, *h1, *pool, *hidden;
    cudaGetSymbolAddress((void**)&agg, g_agg);
    cudaGetSymbolAddress((void**)&h, g_h);
    cudaGetSymbolAddress((void**)&h1, g_h1);
    cudaGetSymbolAddress((void**)&pool, g_pool);
    cudaGetSymbolAddress((void**)&hidden, g_hidden);

    dim3 gemm_node((NN + 127) / 128, 1, 1);     // 391 blocks
    dim3 gemm_read(4, 4, 8);                    // 128 blocks, split-K=8 (Klen=64)
    const int gat_blk = (NN * 32 + 255) / 256;
    const int edge_blk = (NE + 255) / 256;

    // ---- prep: detect dtype, convert, build CSR ----
    zero_all_k<<<1024, 256>>>();
    detect_k<<<64, 256>>>(ei_raw);
    convert_hist_k<<<edge_blk, 256>>>(ei_raw, bat_raw);
    bsum_k<<<NBLK, 256>>>();
    bscan_k<<<1, 256>>>();
    offsets_k<<<NBLK, 256>>>();
    fill_k<<<edge_blk, 256>>>();

    // ---- conv1 ----
    gather_k<<<gat_blk, 256>>>(x);
    gemm_k<0, false, false, true, -1, true><<<gemm_node, 256>>>(agg, c1_W1, c1_b1, h, NN, D, D, D);
    bn_finalize_k<<<1, 128>>>(c1_g, c1_be);
    gemm_k<2, true, false, false, 0, true><<<gemm_node, 256>>>(h, c1_W2, c1_b2, h1, NN, D, D, D);

    // ---- conv2 ----
    gather_k<<<gat_blk, 256>>>(h1);
    gemm_k<0, false, false, true, -1, true><<<gemm_node, 256>>>(agg, c2_W1, c2_b1, h, NN, D, D, D);
    bn_finalize_k<<<1, 128>>>(c2_g, c2_be);
    gemm_k<2, true, false, false, 1, false><<<gemm_node, 256>>>(h, c2_W2, c2_b2, nullptr, NN, D, D, D);

    // ---- readout ----
    gemm_k<0, false, true, false, -1, true><<<gemm_read, 256>>>(pool, lin1_W, nullptr, hidden, NG, 4 * D, 4 * D, 64);
    readout2_k<<<NG, 256>>>(lin1_b, lin2_W, lin2_b, (float*)d_out, out_size);
}

// round 4
// speedup vs baseline: 1.8623x; 1.0706x over previous
#include <cuda_runtime.h>
#include <math.h>
#include <stdint.h>

#define NN 50000
#define NE 600000
#define D  128
#define NG 512
#define BN_EPS 1e-5f
#define NBLK 196   // ceil(NN/256)

// ---------------- scratch (device globals; no allocations) ----------------
__device__ float g_agg[NN * D];      // gather output: sum(neigh) + x
__device__ float g_h[NN * D];        // pre-BN linear output
__device__ float g_h1[NN * D];       // conv1 output
__device__ float g_stats[2 * D];     // sum, sumsq
__device__ float g_aff[2 * D];       // scale, shift
__device__ float g_pool[NG * 4 * D]; // [a1 | a2 | m1 | m2]
__device__ float g_hidden[NG * 4 * D];
__device__ int   g_src[NE];
__device__ int   g_dst[NE];
__device__ int   g_adj[NE];
__device__ int   g_batch[NN];
__device__ int   g_deg[NN];
__device__ int   g_off[NN + 1];
__device__ int   g_cur[NN];
__device__ int   g_bsum[256];
__device__ int   g_boff[256];
__device__ int   g_flag[1];

// ---------------- helpers ----------------
__device__ __forceinline__ uint32_t f2tf32(float x) {
    uint32_t r;
    asm("cvt.rna.tf32.f32 %0, %1;" : "=r"(r) : "f"(x));
    return r;
}

__device__ __forceinline__ void mma_tf32(float* d, const uint32_t* a, const uint32_t* b) {
    asm volatile(
        "mma.sync.aligned.m16n8k8.row.col.f32.tf32.tf32.f32 "
        "{%0,%1,%2,%3}, {%4,%5,%6,%7}, {%8,%9}, {%0,%1,%2,%3};\n"
        : "+f"(d[0]), "+f"(d[1]), "+f"(d[2]), "+f"(d[3])
        : "r"(a[0]), "r"(a[1]), "r"(a[2]), "r"(a[3]), "r"(b[0]), "r"(b[1]));
}

// ---------------- zero + prep ----------------
__global__ void zero_all_k() {
    int i = blockIdx.x * blockDim.x + threadIdx.x;
    if (i < NG * 4 * D) { g_pool[i] = 0.f; g_hidden[i] = 0.f; }
    if (i < NN) g_deg[i] = 0;
    if (i < 2 * D) g_stats[i] = 0.f;
    if (i == 0) g_flag[0] = 0;
}

__global__ void detect_k(const int* __restrict__ w) {
    int tid = blockIdx.x * blockDim.x + threadIdx.x;
    int stride = gridDim.x * blockDim.x;
    int v = 0;
    for (int i = tid; i < NE; i += stride) v |= w[2 * i + 1];
    #pragma unroll
    for (int o = 16; o > 0; o >>= 1) v |= __shfl_xor_sync(0xffffffffu, v, o);
    if ((threadIdx.x & 31) == 0 && v != 0) atomicOr(&g_flag[0], 1);
}

__global__ void convert_hist_k(const int* __restrict__ ei_raw, const int* __restrict__ batch_raw) {
    bool is64 = (g_flag[0] == 0);
    int i = blockIdx.x * blockDim.x + threadIdx.x;
    if (i < NE) {
        int s, d;
        if (is64) { s = ei_raw[2 * i]; d = ei_raw[2 * (NE + i)]; }
        else      { s = ei_raw[i];     d = ei_raw[NE + i]; }
        g_src[i] = s;
        g_dst[i] = d;
        atomicAdd(&g_deg[d], 1);
    }
    if (i < NN) g_batch[i] = is64 ? batch_raw[2 * i] : batch_raw[i];
}

__global__ void bsum_k() {
    __shared__ int s[256];
    int t = threadIdx.x;
    int i = blockIdx.x * 256 + t;
    int v = (i < NN) ? g_deg[i] : 0;
    s[t] = v;
    __syncthreads();
    for (int o = 128; o > 0; o >>= 1) {
        if (t < o) s[t] += s[t + o];
        __syncthreads();
    }
    if (t == 0) g_bsum[blockIdx.x] = s[0];
}

__global__ void bscan_k() {
    __shared__ int s[256];
    int t = threadIdx.x;
    int v = (t < NBLK) ? g_bsum[t] : 0;
    s[t] = v;
    __syncthreads();
    for (int o = 1; o < 256; o <<= 1) {
        int u = (t >= o) ? s[t - o] : 0;
        __syncthreads();
        s[t] += u;
        __syncthreads();
    }
    g_boff[t] = s[t] - v;
}

__global__ void offsets_k() {
    __shared__ int s[256];
    int t = threadIdx.x;
    int i = blockIdx.x * 256 + t;
    int v = (i < NN) ? g_deg[i] : 0;
    s[t] = v;
    __syncthreads();
    for (int o = 1; o < 256; o <<= 1) {
        int u = (t >= o) ? s[t - o] : 0;
        __syncthreads();
        s[t] += u;
        __syncthreads();
    }
    int off = g_boff[blockIdx.x] + s[t] - v;
    if (i < NN) { g_off[i] = off; g_cur[i] = off; }
    if (blockIdx.x == NBLK - 1 && t == 255) g_off[NN] = NE;
}

__global__ void fill_k() {
    int i = blockIdx.x * blockDim.x + threadIdx.x;
    if (i >= NE) return;
    int pos = atomicAdd(&g_cur[g_dst[i]], 1);
    g_adj[pos] = g_src[i];
}

// ---------------- gather: agg = x + sum_{in-edges} X[src] ----------------
__global__ void gather_k(const float* __restrict__ X) {
    int w = (blockIdx.x * blockDim.x + threadIdx.x) >> 5;
    if (w >= NN) return;
    int lane = threadIdx.x & 31;
    int beg = g_off[w], end = g_off[w + 1];
    const float4* X4 = reinterpret_cast<const float4*>(X);
    float4 acc = X4[(size_t)w * 32 + lane];
    int j = beg;
    for (; j + 1 < end; j += 2) {
        int s0 = g_adj[j], s1 = g_adj[j + 1];
        float4 v0 = X4[(size_t)s0 * 32 + lane];
        float4 v1 = X4[(size_t)s1 * 32 + lane];
        acc.x += v0.x; acc.y += v0.y; acc.z += v0.z; acc.w += v0.w;
        acc.x += v1.x; acc.y += v1.y; acc.z += v1.z; acc.w += v1.w;
    }
    if (j < end) {
        int s0 = g_adj[j];
        float4 v0 = X4[(size_t)s0 * 32 + lane];
        acc.x += v0.x; acc.y += v0.y; acc.z += v0.z; acc.w += v0.w;
    }
    reinterpret_cast<float4*>(g_agg)[(size_t)w * 32 + lane] = acc;
}

// ---------------- TF32 tensor-core node GEMM (M x 128 @ 128 x 128) ----------------
// 3xTF32 split: C = Ah*Bh + Ah*Bl + Al*Bh  (fp32-class accuracy)
// Block tile 128x128, full N=K=128. 8 warps; warp (wm,wn) owns 64x32 via
// 4x4 grid of m16n8k8 fragments. Smem stride 20 -> conflict-free frag loads.
// PRE:   0 plain A; 2 relu(A*scale+shift)  (fused BN)
// STATS: column sum/sumsq of output -> g_stats
// POOL:  -1 none; 0/1 fused graph sum/max pooling (layer POOL+1)
// STORE: write C
template <int PRE, bool RELU, bool STATS, int POOL, bool STORE>
__global__ __launch_bounds__(256) void mma_gemm_k(
    const float* __restrict__ A, const float* __restrict__ B,
    const float* __restrict__ bias, float* __restrict__ C, int M)
{
    __shared__ float As_hi[128][20], As_lo[128][20];
    __shared__ float Bs_hi[128][20], Bs_lo[128][20];

    int tid = threadIdx.x;
    int warp = tid >> 5, lane = tid & 31;
    int wm = warp & 1, wn = warp >> 1;
    int row0 = blockIdx.x * 128;
    int lq = lane >> 2;     // 0..7
    int lr = lane & 3;      // 0..3

    float acc[4][4][4];
    #pragma unroll
    for (int i = 0; i < 4; i++)
        #pragma unroll
        for (int j = 0; j < 4; j++)
            #pragma unroll
            for (int r = 0; r < 4; r++) acc[i][j][r] = 0.f;

    for (int k0 = 0; k0 < D; k0 += 16) {
        // ---- stage A (convert + hi/lo split, fused BN prologue) ----
        {
            int r = tid >> 1;
            int ks = (tid & 1) * 8;
            int grow = row0 + r;
            #pragma unroll
            for (int i = 0; i < 2; i++) {
                float4 v = make_float4(0.f, 0.f, 0.f, 0.f);
                int kc = k0 + ks + i * 4;
                if (grow < M) {
                    v = *reinterpret_cast<const float4*>(A + (size_t)grow * D + kc);
                    if (PRE == 2) {
                        v.x = fmaxf(fmaf(v.x, g_aff[kc + 0], g_aff[D + kc + 0]), 0.f);
                        v.y = fmaxf(fmaf(v.y, g_aff[kc + 1], g_aff[D + kc + 1]), 0.f);
                        v.z = fmaxf(fmaf(v.z, g_aff[kc + 2], g_aff[D + kc + 2]), 0.f);
                        v.w = fmaxf(fmaf(v.w, g_aff[kc + 3], g_aff[D + kc + 3]), 0.f);
                    }
                }
                float f[4] = {v.x, v.y, v.z, v.w};
                #pragma unroll
                for (int c = 0; c < 4; c++) {
                    float hi = __uint_as_float(f2tf32(f[c]));
                    As_hi[r][ks + i * 4 + c] = hi;
                    As_lo[r][ks + i * 4 + c] = __uint_as_float(f2tf32(f[c] - hi));
                }
            }
        }
        // ---- stage B transposed [n][k] (convert + split) ----
        {
            int n = tid & 127;
            int kb = (tid >> 7) * 8;
            #pragma unroll
            for (int j = 0; j < 8; j++) {
                float v = B[(size_t)(k0 + kb + j) * D + n];
                float hi = __uint_as_float(f2tf32(v));
                Bs_hi[n][kb + j] = hi;
                Bs_lo[n][kb + j] = __uint_as_float(f2tf32(v - hi));
            }
        }
        __syncthreads();
        // ---- MMA over 2 k-steps of 8 ----
        #pragma unroll
        for (int ks = 0; ks < 16; ks += 8) {
            uint32_t bh[4][2], bl[4][2];
            #pragma unroll
            for (int nf = 0; nf < 4; nf++) {
                int n = wn * 32 + nf * 8 + lq;
                int kk = ks + lr;
                bh[nf][0] = __float_as_uint(Bs_hi[n][kk]);
                bh[nf][1] = __float_as_uint(Bs_hi[n][kk + 4]);
                bl[nf][0] = __float_as_uint(Bs_lo[n][kk]);
                bl[nf][1] = __float_as_uint(Bs_lo[n][kk + 4]);
            }
            #pragma unroll
            for (int mf = 0; mf < 4; mf++) {
                int m = wm * 64 + mf * 16 + lq;
                int kk = ks + lr;
                uint32_t ah[4], al[4];
                ah[0] = __float_as_uint(As_hi[m][kk]);
                ah[1] = __float_as_uint(As_hi[m + 8][kk]);
                ah[2] = __float_as_uint(As_hi[m][kk + 4]);
                ah[3] = __float_as_uint(As_hi[m + 8][kk + 4]);
                al[0] = __float_as_uint(As_lo[m][kk]);
                al[1] = __float_as_uint(As_lo[m + 8][kk]);
                al[2] = __float_as_uint(As_lo[m][kk + 4]);
                al[3] = __float_as_uint(As_lo[m + 8][kk + 4]);
                #pragma unroll
                for (int nf = 0; nf < 4; nf++) {
                    mma_tf32(acc[mf][nf], ah, bh[nf]);
                    mma_tf32(acc[mf][nf], ah, bl[nf]);
                    mma_tf32(acc[mf][nf], al, bh[nf]);
                }
            }
        }
        __syncthreads();
    }

    // ---- epilogue ----
    float bv[4][2];
    int colb[4];
    #pragma unroll
    for (int nf = 0; nf < 4; nf++) {
        colb[nf] = wn * 32 + nf * 8 + 2 * lr;
        bv[nf][0] = bias[colb[nf]];
        bv[nf][1] = bias[colb[nf] + 1];
    }
    float csum[4][2], csq[4][2];
    if (STATS) {
        #pragma unroll
        for (int nf = 0; nf < 4; nf++) { csum[nf][0] = csum[nf][1] = 0.f; csq[nf][0] = csq[nf][1] = 0.f; }
    }
    #pragma unroll
    for (int mf = 0; mf < 4; mf++) {
        #pragma unroll
        for (int rh = 0; rh < 2; rh++) {
            int grow = row0 + wm * 64 + mf * 16 + lq + rh * 8;
            if (grow < M) {
                int bidx = 0;
                if (POOL >= 0) bidx = g_batch[grow];
                #pragma unroll
                for (int nf = 0; nf < 4; nf++) {
                    float v0 = acc[mf][nf][rh * 2 + 0] + bv[nf][0];
                    float v1 = acc[mf][nf][rh * 2 + 1] + bv[nf][1];
                    if (RELU) { v0 = fmaxf(v0, 0.f); v1 = fmaxf(v1, 0.f); }
                    if (STATS) {
                        csum[nf][0] += v0; csum[nf][1] += v1;
                        csq[nf][0] = fmaf(v0, v0, csq[nf][0]);
                        csq[nf][1] = fmaf(v1, v1, csq[nf][1]);
                    }
                    if (STORE) {
                        *reinterpret_cast<float2*>(C + (size_t)grow * D + colb[nf]) =
                            make_float2(v0, v1);
                    }
                    if (POOL >= 0) {
                        float* sb = g_pool + (size_t)bidx * (4 * D) + POOL * D + colb[nf];
                        int*   mb = reinterpret_cast<int*>(
                            g_pool + (size_t)bidx * (4 * D) + (2 + POOL) * D + colb[nf]);
                        atomicAdd(sb + 0, v0);
                        atomicAdd(sb + 1, v1);
                        atomicMax(mb + 0, __float_as_int(v0));
                        atomicMax(mb + 1, __float_as_int(v1));
                    }
                }
            }
        }
    }
    if (STATS) {
        float* sred = &As_hi[0][0];  // 256 floats, reuse
        sred[tid] = 0.f;
        __syncthreads();
        #pragma unroll
        for (int nf = 0; nf < 4; nf++) {
            atomicAdd(&sred[colb[nf]], csum[nf][0]);
            atomicAdd(&sred[colb[nf] + 1], csum[nf][1]);
            atomicAdd(&sred[128 + colb[nf]], csq[nf][0]);
            atomicAdd(&sred[128 + colb[nf] + 1], csq[nf][1]);
        }
        __syncthreads();
        atomicAdd(&g_stats[tid], sred[tid]);
    }
}

__global__ void bn_finalize_k(const float* __restrict__ gamma, const float* __restrict__ beta) {
    int c = threadIdx.x;
    float mu = g_stats[c] * (1.f / NN);
    float var = g_stats[D + c] * (1.f / NN) - mu * mu;
    float sc = gamma[c] * rsqrtf(var + BN_EPS);
    g_aff[c] = sc;
    g_aff[D + c] = beta[c] - mu * sc;
    g_stats[c] = 0.f;
    g_stats[D + c] = 0.f;
}

// ---------------- readout GEMM (split-K fp32, atomic accumulate) ----------------
__global__ __launch_bounds__(256) void rgemm_k(
    const float* __restrict__ A, const float* __restrict__ B,
    float* __restrict__ C, int M, int lda, int NC, int Klen)
{
    __shared__ float As[8][132];
    __shared__ float Bs[8][128];

    int tid = threadIdx.x;
    int row0 = blockIdx.x * 128;
    int col0 = blockIdx.y * 128;
    int k0 = blockIdx.z * Klen;

    int ar = tid >> 1;
    int aseg = (tid & 1) * 4;
    int bk = tid >> 5;
    int bc = (tid & 31) * 4;
    int ty = tid >> 4;
    int tx = tid & 15;

    float acc[8][8];
    #pragma unroll
    for (int i = 0; i < 8; i++)
        #pragma unroll
        for (int j = 0; j < 8; j++) acc[i][j] = 0.f;

    for (int kk = 0; kk < Klen; kk += 8) {
        {
            int grow = row0 + ar;
            float4 v = make_float4(0.f, 0.f, 0.f, 0.f);
            if (grow < M)
                v = *reinterpret_cast<const float4*>(A + (size_t)grow * lda + k0 + kk + aseg);
            As[aseg + 0][ar] = v.x;
            As[aseg + 1][ar] = v.y;
            As[aseg + 2][ar] = v.z;
            As[aseg + 3][ar] = v.w;
        }
        {
            float4 v = *reinterpret_cast<const float4*>(B + (size_t)(k0 + kk + bk) * NC + col0 + bc);
            *reinterpret_cast<float4*>(&Bs[bk][bc]) = v;
        }
        __syncthreads();
        #pragma unroll
        for (int k = 0; k < 8; k++) {
            float4 a0 = *reinterpret_cast<const float4*>(&As[k][ty * 4]);
            float4 a1 = *reinterpret_cast<const float4*>(&As[k][ty * 4 + 64]);
            float4 b0 = *reinterpret_cast<const float4*>(&Bs[k][tx * 4]);
            float4 b1 = *reinterpret_cast<const float4*>(&Bs[k][tx * 4 + 64]);
            float av[8] = {a0.x, a0.y, a0.z, a0.w, a1.x, a1.y, a1.z, a1.w};
            float bvv[8] = {b0.x, b0.y, b0.z, b0.w, b1.x, b1.y, b1.z, b1.w};
            #pragma unroll
            for (int i = 0; i < 8; i++)
                #pragma unroll
                for (int j = 0; j < 8; j++)
                    acc[i][j] = fmaf(av[i], bvv[j], acc[i][j]);
        }
        __syncthreads();
    }
    #pragma unroll
    for (int i = 0; i < 8; i++) {
        int grow = row0 + ty * 4 + (i < 4 ? i : 60 + i);
        if (grow < M) {
            #pragma unroll
            for (int j = 0; j < 8; j++) {
                int gcol = col0 + tx * 4 + (j < 4 ? j : 60 + j);
                atomicAdd(&C[(size_t)grow * NC + gcol], acc[i][j]);
            }
        }
    }
}

// ---------------- final: relu(hidden + b1) . W2 + b2 -> sigmoid ----------------
__global__ void readout2_k(const float* __restrict__ b1, const float* __restrict__ W2,
                           const float* __restrict__ b2,
                           float* __restrict__ out, int out_size) {
    __shared__ float red[8];
    int g = blockIdx.x, tid = threadIdx.x;
    const float* row = g_hidden + (size_t)g * 512;
    float v0 = fmaxf(row[tid] + b1[tid], 0.f) * W2[tid];
    float v1 = fmaxf(row[256 + tid] + b1[256 + tid], 0.f) * W2[256 + tid];
    float s = v0 + v1;
    #pragma unroll
    for (int o = 16; o > 0; o >>= 1) s += __shfl_down_sync(0xffffffffu, s, o);
    if ((tid & 31) == 0) red[tid >> 5] = s;
    __syncthreads();
    if (tid < 8) {
        float t = red[tid];
        #pragma unroll
        for (int o = 4; o > 0; o >>= 1) t += __shfl_down_sync(0xffu, t, o);
        if (tid == 0) {
            float logit = t + b2[0];
            if (out_size >= NG) out[g] = 1.f / (1.f + expf(-logit));
            if (out_size >= 2 * NG) out[NG + g] = logit;
        }
    }
}

// ---------------- launch ----------------
extern "C" void kernel_launch(void* const* d_in, const int* in_sizes, int n_in,
                              void* d_out, int out_size) {
    const float* x       = (const float*)d_in[0];
    const int*   ei_raw  = (const int*)d_in[1];
    const int*   bat_raw = (const int*)d_in[2];
    const float* c1_W1 = (const float*)d_in[3];
    const float* c1_b1 = (const float*)d_in[4];
    const float* c1_g  = (const float*)d_in[5];
    const float* c1_be = (const float*)d_in[6];
    const float* c1_W2 = (const float*)d_in[7];
    const float* c1_b2 = (const float*)d_in[8];
    const float* c2_W1 = (const float*)d_in[9];
    const float* c2_b1 = (const float*)d_in[10];
    const float* c2_g  = (const float*)d_in[11];
    const float* c2_be = (const float*)d_in[12];
    const float* c2_W2 = (const float*)d_in[13];
    const float* c2_b2 = (const float*)d_in[14];
    const float* lin1_W = (const float*)d_in[15];
    const float* lin1_b = (const float*)d_in[16];
    const float* lin2_W = (const float*)d_in[17];
    const float* lin2_b = (const float*)d_in[18];

    float *agg, *h, *h1, *pool, *hidden;
    cudaGetSymbolAddress((void**)&agg, g_agg);
    cudaGetSymbolAddress((void**)&h, g_h);
    cudaGetSymbolAddress((void**)&h1, g_h1);
    cudaGetSymbolAddress((void**)&pool, g_pool);
    cudaGetSymbolAddress((void**)&hidden, g_hidden);

    const int node_blk = (NN + 127) / 128;      // 391
    dim3 gemm_read(4, 4, 8);                    // split-K=8 (Klen=64)
    const int gat_blk = (NN * 32 + 255) / 256;
    const int edge_blk = (NE + 255) / 256;

    // ---- prep: detect dtype, convert, build CSR ----
    zero_all_k<<<1024, 256>>>();
    detect_k<<<64, 256>>>(ei_raw);
    convert_hist_k<<<edge_blk, 256>>>(ei_raw, bat_raw);
    bsum_k<<<NBLK, 256>>>();
    bscan_k<<<1, 256>>>();
    offsets_k<<<NBLK, 256>>>();
    fill_k<<<edge_blk, 256>>>();

    // ---- conv1 ----
    gather_k<<<gat_blk, 256>>>(x);
    mma_gemm_k<0, false, true, -1, true><<<node_blk, 256>>>(agg, c1_W1, c1_b1, h, NN);
    bn_finalize_k<<<1, 128>>>(c1_g, c1_be);
    mma_gemm_k<2, true, false, 0, true><<<node_blk, 256>>>(h, c1_W2, c1_b2, h1, NN);

    // ---- conv2 ----
    gather_k<<<gat_blk, 256>>>(h1);
    mma_gemm_k<0, false, true, -1, true><<<node_blk, 256>>>(agg, c2_W1, c2_b1, h, NN);
    bn_finalize_k<<<1, 128>>>(c2_g, c2_be);
    mma_gemm_k<2, true, false, 1, false><<<node_blk, 256>>>(h, c2_W2, c2_b2, nullptr, NN);

    // ---- readout ----
    rgemm_k<<<gemm_read, 256>>>(pool, lin1_W, hidden, NG, 4 * D, 4 * D, 64);
    readout2_k<<<NG, 256>>>(lin1_b, lin2_W, lin2_b, (float*)d_out, out_size);
}

// round 5
// speedup vs baseline: 1.9320x; 1.0374x over previous
#include <cuda_runtime.h>
#include <math.h>
#include <stdint.h>

#define NN 50000
#define NE 600000
#define D  128
#define NG 512
#define BN_EPS 1e-5f
#define CAP 128   // per-node in-edge bucket capacity (P(deg>128) ~ 0)

// ---------------- scratch (device globals; no allocations) ----------------
__device__ float g_agg[NN * D];
__device__ float g_h[NN * D];
__device__ float g_h1[NN * D];
__device__ float g_stats[2 * D];
__device__ float g_aff[2 * D];
__device__ float g_pool[NG * 4 * D];
__device__ float g_hidden[NG * 4 * D];
__device__ int   g_adjb[NN * CAP];    // bucket CSR: srcs of in-edges per node
__device__ int   g_batch[NN];
__device__ int   g_deg[NN];
__device__ int   g_flag[1];
__device__ float g_wh[4 * 8 * 128 * 16];  // weights hi, chunk-blocked [w][kchunk][n][k16]
__device__ float g_wl[4 * 8 * 128 * 16];  // weights lo

// ---------------- helpers ----------------
__device__ __forceinline__ uint32_t f2tf32(float x) {
    uint32_t r;
    asm("cvt.rna.tf32.f32 %0, %1;" : "=r"(r) : "f"(x));
    return r;
}

__device__ __forceinline__ void mma_tf32(float* d, const uint32_t* a, const uint32_t* b) {
    asm volatile(
        "mma.sync.aligned.m16n8k8.row.col.f32.tf32.tf32.f32 "
        "{%0,%1,%2,%3}, {%4,%5,%6,%7}, {%8,%9}, {%0,%1,%2,%3};\n"
        : "+f"(d[0]), "+f"(d[1]), "+f"(d[2]), "+f"(d[3])
        : "r"(a[0]), "r"(a[1]), "r"(a[2]), "r"(a[3]), "r"(b[0]), "r"(b[1]));
}

// ---------------- zero + weight split (fused) ----------------
// wT layout: g_wh[w][c][n][kk], global k = c*16+kk; source W is [K][N] row-major
__global__ void zero_split_k(const float* __restrict__ W0, const float* __restrict__ W1,
                             const float* __restrict__ W2, const float* __restrict__ W3) {
    int i = blockIdx.x * blockDim.x + threadIdx.x;
    if (i < NG * 4 * D) { g_pool[i] = 0.f; g_hidden[i] = 0.f; }
    if (i < NN) g_deg[i] = 0;
    if (i < 2 * D) g_stats[i] = 0.f;
    if (i == 0) g_flag[0] = 0;
    if (i < 4 * 8 * 128 * 16) {
        int w = i >> 14;
        int r = i & 16383;
        int c = r >> 11;
        int r2 = r & 2047;
        int n = r2 >> 4;
        int kk = r2 & 15;
        const float* Wsrc = (w == 0) ? W0 : (w == 1) ? W1 : (w == 2) ? W2 : W3;
        float v = Wsrc[(size_t)(c * 16 + kk) * D + n];
        float hi = __uint_as_float(f2tf32(v));
        g_wh[i] = hi;
        g_wl[i] = __uint_as_float(f2tf32(v - hi));
    }
}

// ---------------- dtype detect ----------------
__global__ void detect_k(const int* __restrict__ w) {
    int tid = blockIdx.x * blockDim.x + threadIdx.x;
    int stride = gridDim.x * blockDim.x;
    int v = 0;
    for (int i = tid; i < NE; i += stride) v |= w[2 * i + 1];
    #pragma unroll
    for (int o = 16; o > 0; o >>= 1) v |= __shfl_xor_sync(0xffffffffu, v, o);
    if ((threadIdx.x & 31) == 0 && v != 0) atomicOr(&g_flag[0], 1);
}

// ---------------- convert + bucket-fill (single pass over edges) ----------------
__global__ void convert_fill_k(const int* __restrict__ ei_raw, const int* __restrict__ batch_raw) {
    bool is64 = (g_flag[0] == 0);
    int i = blockIdx.x * blockDim.x + threadIdx.x;
    if (i < NE) {
        int s, d;
        if (is64) { s = ei_raw[2 * i]; d = ei_raw[2 * (NE + i)]; }
        else      { s = ei_raw[i];     d = ei_raw[NE + i]; }
        int pos = atomicAdd(&g_deg[d], 1);
        if (pos < CAP) g_adjb[d * CAP + pos] = s;
    }
    if (i < NN) g_batch[i] = is64 ? batch_raw[2 * i] : batch_raw[i];
}

// ---------------- gather: agg = x + sum_{in-edges} X[src]  (4x unrolled) ----------------
__global__ void gather_k(const float* __restrict__ X) {
    int w = (blockIdx.x * blockDim.x + threadIdx.x) >> 5;
    if (w >= NN) return;
    int lane = threadIdx.x & 31;
    int deg = g_deg[w];
    if (deg > CAP) deg = CAP;
    const int* bucket = g_adjb + (size_t)w * CAP;
    const float4* X4 = reinterpret_cast<const float4*>(X);
    float4 acc = X4[(size_t)w * 32 + lane];
    int j = 0;
    for (; j + 4 <= deg; j += 4) {
        int s0 = bucket[j], s1 = bucket[j + 1], s2 = bucket[j + 2], s3 = bucket[j + 3];
        float4 v0 = X4[(size_t)s0 * 32 + lane];
        float4 v1 = X4[(size_t)s1 * 32 + lane];
        float4 v2 = X4[(size_t)s2 * 32 + lane];
        float4 v3 = X4[(size_t)s3 * 32 + lane];
        acc.x += v0.x + v1.x + v2.x + v3.x;
        acc.y += v0.y + v1.y + v2.y + v3.y;
        acc.z += v0.z + v1.z + v2.z + v3.z;
        acc.w += v0.w + v1.w + v2.w + v3.w;
    }
    for (; j < deg; j++) {
        int s0 = bucket[j];
        float4 v0 = X4[(size_t)s0 * 32 + lane];
        acc.x += v0.x; acc.y += v0.y; acc.z += v0.z; acc.w += v0.w;
    }
    reinterpret_cast<float4*>(g_agg)[(size_t)w * 32 + lane] = acc;
}

// ---------------- TF32 tensor-core node GEMM (M x 128 @ 128 x 128, 3xTF32) ----------------
// Block 128x128 full-K; 8 warps, each 64x32 via 4x4 m16n8k8 fragments.
// B comes pre-split (g_wh/g_wl chunk-blocked) -> coalesced float4 staging.
// PRE: 0 plain A; 2 relu(A*scale+shift). STATS: col sum/sumsq. POOL: fused pooling. STORE: write C.
template <int PRE, bool RELU, bool STATS, int POOL, bool STORE>
__global__ __launch_bounds__(256) void mma_gemm_k(
    const float* __restrict__ A, const float* __restrict__ Bh8,
    const float* __restrict__ Bl8, const float* __restrict__ bias,
    float* __restrict__ C, int M)
{
    __shared__ float As_hi[128][20], As_lo[128][20];
    __shared__ float Bs_hi[128][20], Bs_lo[128][20];

    int tid = threadIdx.x;
    int warp = tid >> 5, lane = tid & 31;
    int wm = warp & 1, wn = warp >> 1;
    int row0 = blockIdx.x * 128;
    int lq = lane >> 2;
    int lr = lane & 3;

    float acc[4][4][4];
    #pragma unroll
    for (int i = 0; i < 4; i++)
        #pragma unroll
        for (int j = 0; j < 4; j++)
            #pragma unroll
            for (int r = 0; r < 4; r++) acc[i][j][r] = 0.f;

    for (int k0 = 0; k0 < D; k0 += 16) {
        // ---- stage A (convert + hi/lo split, fused BN prologue) ----
        {
            int r = tid >> 1;
            int ks = (tid & 1) * 8;
            int grow = row0 + r;
            #pragma unroll
            for (int i = 0; i < 2; i++) {
                float4 v = make_float4(0.f, 0.f, 0.f, 0.f);
                int kc = k0 + ks + i * 4;
                if (grow < M) {
                    v = *reinterpret_cast<const float4*>(A + (size_t)grow * D + kc);
                    if (PRE == 2) {
                        v.x = fmaxf(fmaf(v.x, g_aff[kc + 0], g_aff[D + kc + 0]), 0.f);
                        v.y = fmaxf(fmaf(v.y, g_aff[kc + 1], g_aff[D + kc + 1]), 0.f);
                        v.z = fmaxf(fmaf(v.z, g_aff[kc + 2], g_aff[D + kc + 2]), 0.f);
                        v.w = fmaxf(fmaf(v.w, g_aff[kc + 3], g_aff[D + kc + 3]), 0.f);
                    }
                }
                float f[4] = {v.x, v.y, v.z, v.w};
                #pragma unroll
                for (int c = 0; c < 4; c++) {
                    float hi = __uint_as_float(f2tf32(f[c]));
                    As_hi[r][ks + i * 4 + c] = hi;
                    As_lo[r][ks + i * 4 + c] = __uint_as_float(f2tf32(f[c] - hi));
                }
            }
        }
        // ---- stage B from pre-split chunk-blocked weights (coalesced) ----
        {
            const float* bh = Bh8 + (k0 >> 4) * 2048 + tid * 8;
            const float* bl = Bl8 + (k0 >> 4) * 2048 + tid * 8;
            float4 h0 = *reinterpret_cast<const float4*>(bh);
            float4 h1 = *reinterpret_cast<const float4*>(bh + 4);
            float4 l0 = *reinterpret_cast<const float4*>(bl);
            float4 l1 = *reinterpret_cast<const float4*>(bl + 4);
            int n = tid >> 1;
            int kb = (tid & 1) * 8;
            Bs_hi[n][kb + 0] = h0.x; Bs_hi[n][kb + 1] = h0.y;
            Bs_hi[n][kb + 2] = h0.z; Bs_hi[n][kb + 3] = h0.w;
            Bs_hi[n][kb + 4] = h1.x; Bs_hi[n][kb + 5] = h1.y;
            Bs_hi[n][kb + 6] = h1.z; Bs_hi[n][kb + 7] = h1.w;
            Bs_lo[n][kb + 0] = l0.x; Bs_lo[n][kb + 1] = l0.y;
            Bs_lo[n][kb + 2] = l0.z; Bs_lo[n][kb + 3] = l0.w;
            Bs_lo[n][kb + 4] = l1.x; Bs_lo[n][kb + 5] = l1.y;
            Bs_lo[n][kb + 6] = l1.z; Bs_lo[n][kb + 7] = l1.w;
        }
        __syncthreads();
        // ---- MMA over 2 k-steps of 8 ----
        #pragma unroll
        for (int ks = 0; ks < 16; ks += 8) {
            uint32_t bh[4][2], bl[4][2];
            #pragma unroll
            for (int nf = 0; nf < 4; nf++) {
                int n = wn * 32 + nf * 8 + lq;
                int kk = ks + lr;
                bh[nf][0] = __float_as_uint(Bs_hi[n][kk]);
                bh[nf][1] = __float_as_uint(Bs_hi[n][kk + 4]);
                bl[nf][0] = __float_as_uint(Bs_lo[n][kk]);
                bl[nf][1] = __float_as_uint(Bs_lo[n][kk + 4]);
            }
            #pragma unroll
            for (int mf = 0; mf < 4; mf++) {
                int m = wm * 64 + mf * 16 + lq;
                int kk = ks + lr;
                uint32_t ah[4], al[4];
                ah[0] = __float_as_uint(As_hi[m][kk]);
                ah[1] = __float_as_uint(As_hi[m + 8][kk]);
                ah[2] = __float_as_uint(As_hi[m][kk + 4]);
                ah[3] = __float_as_uint(As_hi[m + 8][kk + 4]);
                al[0] = __float_as_uint(As_lo[m][kk]);
                al[1] = __float_as_uint(As_lo[m + 8][kk]);
                al[2] = __float_as_uint(As_lo[m][kk + 4]);
                al[3] = __float_as_uint(As_lo[m + 8][kk + 4]);
                #pragma unroll
                for (int nf = 0; nf < 4; nf++) {
                    mma_tf32(acc[mf][nf], ah, bh[nf]);
                    mma_tf32(acc[mf][nf], ah, bl[nf]);
                    mma_tf32(acc[mf][nf], al, bh[nf]);
                }
            }
        }
        __syncthreads();
    }

    // ---- epilogue ----
    float bv[4][2];
    int colb[4];
    #pragma unroll
    for (int nf = 0; nf < 4; nf++) {
        colb[nf] = wn * 32 + nf * 8 + 2 * lr;
        bv[nf][0] = bias[colb[nf]];
        bv[nf][1] = bias[colb[nf] + 1];
    }
    float csum[4][2], csq[4][2];
    if (STATS) {
        #pragma unroll
        for (int nf = 0; nf < 4; nf++) { csum[nf][0] = csum[nf][1] = 0.f; csq[nf][0] = csq[nf][1] = 0.f; }
    }
    #pragma unroll
    for (int mf = 0; mf < 4; mf++) {
        #pragma unroll
        for (int rh = 0; rh < 2; rh++) {
            int grow = row0 + wm * 64 + mf * 16 + lq + rh * 8;
            if (grow < M) {
                int bidx = 0;
                if (POOL >= 0) bidx = g_batch[grow];
                #pragma unroll
                for (int nf = 0; nf < 4; nf++) {
                    float v0 = acc[mf][nf][rh * 2 + 0] + bv[nf][0];
                    float v1 = acc[mf][nf][rh * 2 + 1] + bv[nf][1];
                    if (RELU) { v0 = fmaxf(v0, 0.f); v1 = fmaxf(v1, 0.f); }
                    if (STATS) {
                        csum[nf][0] += v0; csum[nf][1] += v1;
                        csq[nf][0] = fmaf(v0, v0, csq[nf][0]);
                        csq[nf][1] = fmaf(v1, v1, csq[nf][1]);
                    }
                    if (STORE) {
                        *reinterpret_cast<float2*>(C + (size_t)grow * D + colb[nf]) =
                            make_float2(v0, v1);
                    }
                    if (POOL >= 0) {
                        float* sb = g_pool + (size_t)bidx * (4 * D) + POOL * D + colb[nf];
                        int*   mb = reinterpret_cast<int*>(
                            g_pool + (size_t)bidx * (4 * D) + (2 + POOL) * D + colb[nf]);
                        atomicAdd(sb + 0, v0);
                        atomicAdd(sb + 1, v1);
                        atomicMax(mb + 0, __float_as_int(v0));
                        atomicMax(mb + 1, __float_as_int(v1));
                    }
                }
            }
        }
    }
    if (STATS) {
        float* sred = &As_hi[0][0];
        sred[tid] = 0.f;
        __syncthreads();
        #pragma unroll
        for (int nf = 0; nf < 4; nf++) {
            atomicAdd(&sred[colb[nf]], csum[nf][0]);
            atomicAdd(&sred[colb[nf] + 1], csum[nf][1]);
            atomicAdd(&sred[128 + colb[nf]], csq[nf][0]);
            atomicAdd(&sred[128 + colb[nf] + 1], csq[nf][1]);
        }
        __syncthreads();
        atomicAdd(&g_stats[tid], sred[tid]);
    }
}

__global__ void bn_finalize_k(const float* __restrict__ gamma, const float* __restrict__ beta) {
    int c = threadIdx.x;
    float mu = g_stats[c] * (1.f / NN);
    float var = g_stats[D + c] * (1.f / NN) - mu * mu;
    float sc = gamma[c] * rsqrtf(var + BN_EPS);
    g_aff[c] = sc;
    g_aff[D + c] = beta[c] - mu * sc;
    g_stats[c] = 0.f;
    g_stats[D + c] = 0.f;
}

// ---------------- readout GEMM (split-K fp32, atomic accumulate) ----------------
__global__ __launch_bounds__(256) void rgemm_k(
    const float* __restrict__ A, const float* __restrict__ B,
    float* __restrict__ C, int M, int lda, int NC, int Klen)
{
    __shared__ float As[8][132];
    __shared__ float Bs[8][128];

    int tid = threadIdx.x;
    int row0 = blockIdx.x * 128;
    int col0 = blockIdx.y * 128;
    int k0 = blockIdx.z * Klen;

    int ar = tid >> 1;
    int aseg = (tid & 1) * 4;
    int bk = tid >> 5;
    int bc = (tid & 31) * 4;
    int ty = tid >> 4;
    int tx = tid & 15;

    float acc[8][8];
    #pragma unroll
    for (int i = 0; i < 8; i++)
        #pragma unroll
        for (int j = 0; j < 8; j++) acc[i][j] = 0.f;

    for (int kk = 0; kk < Klen; kk += 8) {
        {
            int grow = row0 + ar;
            float4 v = make_float4(0.f, 0.f, 0.f, 0.f);
            if (grow < M)
                v = *reinterpret_cast<const float4*>(A + (size_t)grow * lda + k0 + kk + aseg);
            As[aseg + 0][ar] = v.x;
            As[aseg + 1][ar] = v.y;
            As[aseg + 2][ar] = v.z;
            As[aseg + 3][ar] = v.w;
        }
        {
            float4 v = *reinterpret_cast<const float4*>(B + (size_t)(k0 + kk + bk) * NC + col0 + bc);
            *reinterpret_cast<float4*>(&Bs[bk][bc]) = v;
        }
        __syncthreads();
        #pragma unroll
        for (int k = 0; k < 8; k++) {
            float4 a0 = *reinterpret_cast<const float4*>(&As[k][ty * 4]);
            float4 a1 = *reinterpret_cast<const float4*>(&As[k][ty * 4 + 64]);
            float4 b0 = *reinterpret_cast<const float4*>(&Bs[k][tx * 4]);
            float4 b1 = *reinterpret_cast<const float4*>(&Bs[k][tx * 4 + 64]);
            float av[8] = {a0.x, a0.y, a0.z, a0.w, a1.x, a1.y, a1.z, a1.w};
            float bvv[8] = {b0.x, b0.y, b0.z, b0.w, b1.x, b1.y, b1.z, b1.w};
            #pragma unroll
            for (int i = 0; i < 8; i++)
                #pragma unroll
                for (int j = 0; j < 8; j++)
                    acc[i][j] = fmaf(av[i], bvv[j], acc[i][j]);
        }
        __syncthreads();
    }
    #pragma unroll
    for (int i = 0; i < 8; i++) {
        int grow = row0 + ty * 4 + (i < 4 ? i : 60 + i);
        if (grow < M) {
            #pragma unroll
            for (int j = 0; j < 8; j++) {
                int gcol = col0 + tx * 4 + (j < 4 ? j : 60 + j);
                atomicAdd(&C[(size_t)grow * NC + gcol], acc[i][j]);
            }
        }
    }
}

// ---------------- final: relu(hidden + b1) . W2 + b2 -> sigmoid ----------------
__global__ void readout2_k(const float* __restrict__ b1, const float* __restrict__ W2,
                           const float* __restrict__ b2,
                           float* __restrict__ out, int out_size) {
    __shared__ float red[8];
    int g = blockIdx.x, tid = threadIdx.x;
    const float* row = g_hidden + (size_t)g * 512;
    float v0 = fmaxf(row[tid] + b1[tid], 0.f) * W2[tid];
    float v1 = fmaxf(row[256 + tid] + b1[256 + tid], 0.f) * W2[256 + tid];
    float s = v0 + v1;
    #pragma unroll
    for (int o = 16; o > 0; o >>= 1) s += __shfl_down_sync(0xffffffffu, s, o);
    if ((tid & 31) == 0) red[tid >> 5] = s;
    __syncthreads();
    if (tid < 8) {
        float t = red[tid];
        #pragma unroll
        for (int o = 4; o > 0; o >>= 1) t += __shfl_down_sync(0xffu, t, o);
        if (tid == 0) {
            float logit = t + b2[0];
            if (out_size >= NG) out[g] = 1.f / (1.f + expf(-logit));
            if (out_size >= 2 * NG) out[NG + g] = logit;
        }
    }
}

// ---------------- launch ----------------
extern "C" void kernel_launch(void* const* d_in, const int* in_sizes, int n_in,
                              void* d_out, int out_size) {
    const float* x       = (const float*)d_in[0];
    const int*   ei_raw  = (const int*)d_in[1];
    const int*   bat_raw = (const int*)d_in[2];
    const float* c1_W1 = (const float*)d_in[3];
    const float* c1_b1 = (const float*)d_in[4];
    const float* c1_g  = (const float*)d_in[5];
    const float* c1_be = (const float*)d_in[6];
    const float* c1_W2 = (const float*)d_in[7];
    const float* c1_b2 = (const float*)d_in[8];
    const float* c2_W1 = (const float*)d_in[9];
    const float* c2_b1 = (const float*)d_in[10];
    const float* c2_g  = (const float*)d_in[11];
    const float* c2_be = (const float*)d_in[12];
    const float* c2_W2 = (const float*)d_in[13];
    const float* c2_b2 = (const float*)d_in[14];
    const float* lin1_W = (const float*)d_in[15];
    const float* lin1_b = (const float*)d_in[16];
    const float* lin2_W = (const float*)d_in[17];
    const float* lin2_b = (const float*)d_in[18];

    float *agg, *h, *h1, *pool, *hidden, *wh, *wl;
    cudaGetSymbolAddress((void**)&agg, g_agg);
    cudaGetSymbolAddress((void**)&h, g_h);
    cudaGetSymbolAddress((void**)&h1, g_h1);
    cudaGetSymbolAddress((void**)&pool, g_pool);
    cudaGetSymbolAddress((void**)&hidden, g_hidden);
    cudaGetSymbolAddress((void**)&wh, g_wh);
    cudaGetSymbolAddress((void**)&wl, g_wl);

    const int node_blk = (NN + 127) / 128;      // 391
    dim3 gemm_read(4, 4, 8);                    // split-K=8 (Klen=64)
    const int gat_blk = (NN * 32 + 255) / 256;
    const int edge_blk = (NE + 255) / 256;
    const int WSZ = 8 * 128 * 16;               // per-weight split size

    // ---- prep ----
    zero_split_k<<<1024, 256>>>(c1_W1, c1_W2, c2_W1, c2_W2);
    detect_k<<<64, 256>>>(ei_raw);
    convert_fill_k<<<edge_blk, 256>>>(ei_raw, bat_raw);

    // ---- conv1 ----
    gather_k<<<gat_blk, 256>>>(x);
    mma_gemm_k<0, false, true, -1, true><<<node_blk, 256>>>(agg, wh + 0 * WSZ, wl + 0 * WSZ, c1_b1, h, NN);
    bn_finalize_k<<<1, 128>>>(c1_g, c1_be);
    mma_gemm_k<2, true, false, 0, true><<<node_blk, 256>>>(h, wh + 1 * WSZ, wl + 1 * WSZ, c1_b2, h1, NN);

    // ---- conv2 ----
    gather_k<<<gat_blk, 256>>>(h1);
    mma_gemm_k<0, false, true, -1, true><<<node_blk, 256>>>(agg, wh + 2 * WSZ, wl + 2 * WSZ, c2_b1, h, NN);
    bn_finalize_k<<<1, 128>>>(c2_g, c2_be);
    mma_gemm_k<2, true, false, 1, false><<<node_blk, 256>>>(h, wh + 3 * WSZ, wl + 3 * WSZ, c2_b2, nullptr, NN);

    // ---- readout ----
    rgemm_k<<<gemm_read, 256>>>(pool, lin1_W, hidden, NG, 4 * D, 4 * D, 64);
    readout2_k<<<NG, 256>>>(lin1_b, lin2_W, lin2_b, (float*)d_out, out_size);
}